// round 16
// baseline (speedup 1.0000x reference)
#include <cuda_runtime.h>
#include <cuda_fp16.h>
#include <math.h>
#include <stdint.h>

#define N_NODES   16384
#define N_GRAPHS  64
#define NPG       256
#define F_IN      128
#define E_DIM     256
#define N_HEADS   8
#define DH        32
#define MLP_DIM   1024
#define N_LAYERS  4
#define N_CLASSES 10
#define N_EDGES   262144
#define SEQ       257                 // NODES_PER_GRAPH + 1 (cls)
#define TOK       (N_GRAPHS * SEQ)    // 16448
#define TOKP      16512               // padded to 129*128 for 128-row tiles
#define LN_EPS    1e-5f

// ---------------- scratch (static device globals, zero-initialized) --------
__device__ float g_xw [N_NODES * F_IN];
__device__ float g_dinv[N_NODES];
__device__ float g_emb[N_NODES * E_DIM];
__device__ float g_h  [TOKP * E_DIM];
__device__ float g_qkv[TOKP * 3 * E_DIM];   // reused as fp16 qkv
__device__ float g_tmp[TOKP * E_DIM];

// CSR for GCN gather
__device__ int g_cnt [N_NODES];
__device__ int g_base[N_NODES];
__device__ int g_cur [N_NODES];
__device__ int g_elist[N_EDGES];

// fp16 operand mirrors
__device__ __half g_x16  [N_NODES * F_IN];
__device__ __half g_gcnw16[F_IN * F_IN];
__device__ __half g_gcn16[N_NODES * F_IN];
__device__ __half g_embw16[E_DIM * F_IN];
__device__ __half g_h16  [TOKP * E_DIM];
__device__ __half g_att16[TOKP * E_DIM];
__device__ __half g_mlp16[TOKP * MLP_DIM];
__device__ __half g_inw16 [N_LAYERS * 3 * E_DIM * E_DIM];
__device__ __half g_outw16[N_LAYERS * E_DIM * E_DIM];
__device__ __half g_l1w16 [N_LAYERS * MLP_DIM * E_DIM];
__device__ __half g_l2w16 [N_LAYERS * E_DIM * MLP_DIM];

// ===================== helpers =============================================
__device__ __forceinline__ uint32_t smem_u32(const void* p) {
    return (uint32_t)__cvta_generic_to_shared(p);
}
__device__ __forceinline__ void cp16s(uint32_t dst, const void* src) {
    asm volatile("cp.async.cg.shared.global [%0], [%1], 16;\n" :: "r"(dst), "l"(src));
}
#define CP_COMMIT() asm volatile("cp.async.commit_group;\n")

__device__ __forceinline__ void mma_f16(float* d, const uint32_t* a, const uint32_t* b) {
    asm volatile(
        "mma.sync.aligned.m16n8k16.row.col.f32.f16.f16.f32 "
        "{%0,%1,%2,%3}, {%4,%5,%6,%7}, {%8,%9}, {%0,%1,%2,%3};\n"
        : "+f"(d[0]), "+f"(d[1]), "+f"(d[2]), "+f"(d[3])
        : "r"(a[0]), "r"(a[1]), "r"(a[2]), "r"(a[3]), "r"(b[0]), "r"(b[1]));
}
__device__ __forceinline__ uint32_t packh2(float x, float y) {
    __half2 h = __floats2half2_rn(x, y);
    return *(uint32_t*)&h;
}

// ===================== fp16 HMMA GEMM (2-stage, K-chunk 64, 1 sync/iter) ====
// C[M,N] = A[M,K] * B[N,K]^T; block 128x128x64, 8 warps (2x4), m16n8k16.
// Single __syncthreads per k-iteration: the barrier guarantees load(kt) is
// visible to all warps AND all warps finished compute(kt-1) (last reader of
// stage s^1), so the refill of s^1 issued after the barrier is safe.
#define HROW 72
#define STG  (128 * HROW)               // halves per matrix per stage
#define GH_SMEM (4 * STG * 2)           // 2 stages x (A+B) x 2 bytes = 73728

template <int RELU>
__global__ __launch_bounds__(256, 2)
void gemm_h(const __half* __restrict__ A, const __half* __restrict__ B,
            const float* __restrict__ bias, const float* __restrict__ add,
            float* __restrict__ C32, __half* __restrict__ C16, int N, int K)
{
    extern __shared__ __half smh[];
    __half* As = smh;            // [2][STG]
    __half* Bs = smh + 2 * STG;  // [2][STG]

    const int tid = threadIdx.x;
    const int warp = tid >> 5, lane = tid & 31;
    const int wm = warp >> 2, wn = warp & 3;     // 2 x 4 warp grid
    const int r = lane >> 2, c = lane & 3;
    const int m0 = blockIdx.y * 128;
    const int n0 = blockIdx.x * 128;
    const int KT = K >> 6;                       // 64-wide k-chunks

    float acc[4][4][4];
#pragma unroll
    for (int i = 0; i < 4; i++)
#pragma unroll
        for (int j = 0; j < 4; j++)
#pragma unroll
            for (int q = 0; q < 4; q++) acc[i][j][q] = 0.f;

    auto load_stage = [&](int kt, int s) {
        const __half* Ag = A + (size_t)m0 * K + kt * 64;
        const __half* Bg = B + (size_t)n0 * K + kt * 64;
        const uint32_t sa = smem_u32(&As[s * STG]);
        const uint32_t sb = smem_u32(&Bs[s * STG]);
#pragma unroll
        for (int i = 0; i < 4; i++) {
            int id = tid + 256 * i;
            int row = id >> 3, ch = id & 7;
            cp16s(sa + row * 144 + ch * 16, Ag + (size_t)row * K + ch * 8);
            cp16s(sb + row * 144 + ch * 16, Bg + (size_t)row * K + ch * 8);
        }
    };

    load_stage(0, 0);
    CP_COMMIT();

    for (int kt = 0; kt < KT; kt++) {
        const int s = kt & 1;
        asm volatile("cp.async.wait_group 0;\n");   // load(kt) landed (this thread)
        __syncthreads();                             // visible to all; s^1 free
        if (kt + 1 < KT) {
            load_stage(kt + 1, s ^ 1);
            CP_COMMIT();
        }

        const uint32_t saBase = smem_u32(&As[s * STG]);
        const __half* Bst = &Bs[s * STG];
#pragma unroll
        for (int ks = 0; ks < 4; ks++) {
            uint32_t a[4][4];
#pragma unroll
            for (int ma = 0; ma < 4; ma++) {
                int mbase = wm * 64 + ma * 16;
                uint32_t addr = saBase + (mbase + (lane & 15)) * 144
                              + ks * 32 + ((lane >> 4) & 1) * 16;
                asm volatile(
                    "ldmatrix.sync.aligned.m8n8.x4.shared.b16 {%0,%1,%2,%3}, [%4];"
                    : "=r"(a[ma][0]), "=r"(a[ma][1]), "=r"(a[ma][2]), "=r"(a[ma][3])
                    : "r"(addr));
            }
            uint32_t b[4][2];
#pragma unroll
            for (int na = 0; na < 4; na++) {
                int n = wn * 32 + na * 8 + r;
                const __half* bp = Bst + n * HROW + ks * 16 + c * 2;
                b[na][0] = *(const uint32_t*)(bp);
                b[na][1] = *(const uint32_t*)(bp + 8);
            }
#pragma unroll
            for (int ma = 0; ma < 4; ma++)
#pragma unroll
                for (int na = 0; na < 4; na++)
                    mma_f16(acc[ma][na], a[ma], b[na]);
        }
    }

#pragma unroll
    for (int ma = 0; ma < 4; ma++) {
        int mlo = m0 + wm * 64 + ma * 16 + r;
        int mhi = mlo + 8;
#pragma unroll
        for (int na = 0; na < 4; na++) {
            int n = n0 + wn * 32 + na * 8 + c * 2;
            float b0 = bias ? bias[n] : 0.f;
            float b1 = bias ? bias[n + 1] : 0.f;
            float v0 = acc[ma][na][0] + b0;
            float v1 = acc[ma][na][1] + b1;
            float v2 = acc[ma][na][2] + b0;
            float v3 = acc[ma][na][3] + b1;
            size_t ilo = (size_t)mlo * N + n;
            size_t ihi = (size_t)mhi * N + n;
            if (add) {
                float2 alo = *(const float2*)&add[ilo];
                float2 ahi = *(const float2*)&add[ihi];
                v0 += alo.x; v1 += alo.y; v2 += ahi.x; v3 += ahi.y;
            }
            if (RELU) {
                v0 = v0 > 0.f ? v0 : 0.f; v1 = v1 > 0.f ? v1 : 0.f;
                v2 = v2 > 0.f ? v2 : 0.f; v3 = v3 > 0.f ? v3 : 0.f;
            }
            if (C32) {
                *(float2*)&C32[ilo] = make_float2(v0, v1);
                *(float2*)&C32[ihi] = make_float2(v2, v3);
            }
            if (C16) {
                *(__half2*)&C16[ilo] = __floats2half2_rn(v0, v1);
                *(__half2*)&C16[ihi] = __floats2half2_rn(v2, v3);
            }
        }
    }
}

// ---------------- fp32 -> fp16 convert -------------------------------------
__global__ void cvt_k(const float* __restrict__ s, __half* __restrict__ d, int n) {
    int i = blockIdx.x * blockDim.x + threadIdx.x;
    if (i < n) d[i] = __float2half_rn(s[i]);
}

// ---------------- GCN: CSR build + gather ----------------------------------
__global__ void zero_cnt_k() {
    int i = blockIdx.x * blockDim.x + threadIdx.x;
    if (i < N_NODES) g_cnt[i] = 0;
}
__global__ void count_k(const int* __restrict__ ei) {
    int i = blockIdx.x * blockDim.x + threadIdx.x;
    for (; i < N_EDGES; i += gridDim.x * blockDim.x)
        atomicAdd(&g_cnt[ei[N_EDGES + i]], 1);
}
__global__ __launch_bounds__(1024)
void scan_k() {
    const int t = threadIdx.x, lane = t & 31, wid = t >> 5;
    const unsigned FULL = 0xffffffffu;
    __shared__ int wsum[32];

    int local[16];
    int s = 0;
#pragma unroll
    for (int i = 0; i < 16; i++) { local[i] = s; s += g_cnt[t * 16 + i]; }

    int v = s;
#pragma unroll
    for (int o = 1; o < 32; o <<= 1) {
        int n = __shfl_up_sync(FULL, v, o);
        if (lane >= o) v += n;
    }
    if (lane == 31) wsum[wid] = v;
    __syncthreads();
    if (wid == 0) {
        int w = wsum[lane];
#pragma unroll
        for (int o = 1; o < 32; o <<= 1) {
            int n = __shfl_up_sync(FULL, w, o);
            if (lane >= o) w += n;
        }
        wsum[lane] = w;
    }
    __syncthreads();
    int chunk_base = v - s + (wid ? wsum[wid - 1] : 0);
#pragma unroll
    for (int i = 0; i < 16; i++) {
        int idx = t * 16 + i;
        int b = chunk_base + local[i];
        g_base[idx] = b;
        g_cur[idx]  = b;
        g_dinv[idx] = rsqrtf((float)g_cnt[idx] + 1.0f);
    }
}
__global__ void fill_k(const int* __restrict__ ei) {
    int i = blockIdx.x * blockDim.x + threadIdx.x;
    for (; i < N_EDGES; i += gridDim.x * blockDim.x) {
        int col = ei[N_EDGES + i];
        int pos = atomicAdd(&g_cur[col], 1);
        g_elist[pos] = ei[i];
    }
}
__global__ __launch_bounds__(256)
void gcn_gather_k(const float* __restrict__ bias) {
    const int node = (blockIdx.x * blockDim.x + threadIdx.x) >> 5;
    const int lane = threadIdx.x & 31;

    const float dc = g_dinv[node];
    float4 acc = *(const float4*)(g_xw + (size_t)node * F_IN + lane * 4);
    float sc = dc * dc;
    acc.x *= sc; acc.y *= sc; acc.z *= sc; acc.w *= sc;

    const int nv = g_cnt[node];
    const int b0 = g_base[node];
    for (int i = 0; i < nv; i++) {
        int row = g_elist[b0 + i];
        float nm = dc * g_dinv[row];
        float4 v = *(const float4*)(g_xw + (size_t)row * F_IN + lane * 4);
        acc.x += nm * v.x; acc.y += nm * v.y;
        acc.z += nm * v.z; acc.w += nm * v.w;
    }

    float4 bb = *(const float4*)(bias + lane * 4);
    acc.x += bb.x; acc.y += bb.y; acc.z += bb.z; acc.w += bb.w;
    acc.x = acc.x > 0.f ? acc.x : 0.f;
    acc.y = acc.y > 0.f ? acc.y : 0.f;
    acc.z = acc.z > 0.f ? acc.z : 0.f;
    acc.w = acc.w > 0.f ? acc.w : 0.f;

    __half2 h0 = __floats2half2_rn(acc.x, acc.y);
    __half2 h1 = __floats2half2_rn(acc.z, acc.w);
    *(uint2*)(g_gcn16 + (size_t)node * F_IN + lane * 4) =
        make_uint2(*(uint32_t*)&h0, *(uint32_t*)&h1);
}

// ---------------- assemble H (cls token + embedded nodes) ------------------
__global__ void assemble_k(const float* __restrict__ cls) {
    int idx = blockIdx.x * blockDim.x + threadIdx.x;   // TOK*E_DIM exact
    int row = idx >> 8, col = idx & 255;
    int g = row / SEQ, s = row - g * SEQ;
    float v = (s == 0) ? cls[col]
                       : g_emb[((size_t)(g * NPG + s - 1)) * E_DIM + col];
    g_h[idx] = v;
    g_h16[idx] = __float2half_rn(v);
}

// ============== fp16 flash attention: block per (graph, head) ===============
#define SEQP2 272
#define KSH 40          // Ks stride in halves
#define VSH 280         // Vt stride in halves

__global__ __launch_bounds__(256)
void attn_h_k(const __half* __restrict__ qkv, __half* __restrict__ O)
{
    const int g  = blockIdx.x >> 3;
    const int hd = blockIdx.x & 7;
    __shared__ __half Ks[SEQP2 * KSH];   // [key][d]
    __shared__ __half Vt[32 * VSH];      // [d][key]

    const int tid = threadIdx.x, warp = tid >> 5, lane = tid & 31;
    const int r = lane >> 2, c = lane & 3;
    const float scale = 0.17677669529663687f;   // 1/sqrt(32)
    const unsigned FULL = 0xffffffffu;

    for (int i = tid; i < SEQP2 * 32; i += 256) {
        int key = i >> 5, d = i & 31;
        __half kv = __float2half_rn(0.f), vv = kv;
        if (key < SEQ) {
            const __half* p = qkv + ((size_t)(g * SEQ + key)) * 768 + E_DIM + hd * DH + d;
            kv = p[0]; vv = p[E_DIM];
        }
        Ks[key * KSH + d] = kv;
        Vt[d * VSH + key] = vv;
    }
    __syncthreads();

    for (int qt = warp; qt < 17; qt += 8) {
        const int q0 = qt * 16;
        int row0 = q0 + r;      if (row0 > 256) row0 = 256;
        int row1 = q0 + r + 8;  if (row1 > 256) row1 = 256;
        const __half* Q0 = qkv + ((size_t)(g * SEQ + row0)) * 768 + hd * DH;
        const __half* Q1 = qkv + ((size_t)(g * SEQ + row1)) * 768 + hd * DH;

        uint32_t qa[2][4];
#pragma unroll
        for (int ks = 0; ks < 2; ks++) {
            qa[ks][0] = *(const uint32_t*)&Q0[ks * 16 + 2 * c];
            qa[ks][1] = *(const uint32_t*)&Q1[ks * 16 + 2 * c];
            qa[ks][2] = *(const uint32_t*)&Q0[ks * 16 + 2 * c + 8];
            qa[ks][3] = *(const uint32_t*)&Q1[ks * 16 + 2 * c + 8];
        }

        float m0 = -1e30f, m1 = -1e30f, l0 = 0.f, l1 = 0.f;
        float oa[4][4];
#pragma unroll
        for (int nt = 0; nt < 4; nt++)
#pragma unroll
            for (int q = 0; q < 4; q++) oa[nt][q] = 0.f;

        for (int n0 = 0; n0 < SEQP2; n0 += 16) {
            float st[2][4] = {{0.f,0.f,0.f,0.f},{0.f,0.f,0.f,0.f}};
#pragma unroll
            for (int tile = 0; tile < 2; tile++) {
                int key = n0 + tile * 8 + r;
#pragma unroll
                for (int ks = 0; ks < 2; ks++) {
                    uint32_t b[2];
                    b[0] = *(const uint32_t*)&Ks[key * KSH + ks * 16 + 2 * c];
                    b[1] = *(const uint32_t*)&Ks[key * KSH + ks * 16 + 2 * c + 8];
                    mma_f16(st[tile], qa[ks], b);
                }
            }
#pragma unroll
            for (int tile = 0; tile < 2; tile++) {
                int col = n0 + tile * 8 + 2 * c;
                st[tile][0] = (col     < SEQ) ? st[tile][0] * scale : -1e30f;
                st[tile][1] = (col + 1 < SEQ) ? st[tile][1] * scale : -1e30f;
                st[tile][2] = (col     < SEQ) ? st[tile][2] * scale : -1e30f;
                st[tile][3] = (col + 1 < SEQ) ? st[tile][3] * scale : -1e30f;
            }

            float cm0 = fmaxf(fmaxf(st[0][0], st[0][1]), fmaxf(st[1][0], st[1][1]));
            float cm1 = fmaxf(fmaxf(st[0][2], st[0][3]), fmaxf(st[1][2], st[1][3]));
            cm0 = fmaxf(cm0, __shfl_xor_sync(FULL, cm0, 1));
            cm0 = fmaxf(cm0, __shfl_xor_sync(FULL, cm0, 2));
            cm1 = fmaxf(cm1, __shfl_xor_sync(FULL, cm1, 1));
            cm1 = fmaxf(cm1, __shfl_xor_sync(FULL, cm1, 2));
            float nm0 = fmaxf(m0, cm0), nm1 = fmaxf(m1, cm1);
            float al0 = __expf(m0 - nm0), al1 = __expf(m1 - nm1);
            m0 = nm0; m1 = nm1;
            float p00 = __expf(st[0][0] - nm0), p01 = __expf(st[0][1] - nm0);
            float p02 = __expf(st[0][2] - nm1), p03 = __expf(st[0][3] - nm1);
            float p10 = __expf(st[1][0] - nm0), p11 = __expf(st[1][1] - nm0);
            float p12 = __expf(st[1][2] - nm1), p13 = __expf(st[1][3] - nm1);
            float rs0 = p00 + p01 + p10 + p11;
            float rs1 = p02 + p03 + p12 + p13;
            rs0 += __shfl_xor_sync(FULL, rs0, 1);
            rs0 += __shfl_xor_sync(FULL, rs0, 2);
            rs1 += __shfl_xor_sync(FULL, rs1, 1);
            rs1 += __shfl_xor_sync(FULL, rs1, 2);
            l0 = l0 * al0 + rs0;
            l1 = l1 * al1 + rs1;
#pragma unroll
            for (int nt = 0; nt < 4; nt++) {
                oa[nt][0] *= al0; oa[nt][1] *= al0;
                oa[nt][2] *= al1; oa[nt][3] *= al1;
            }

            uint32_t pa[4];
            pa[0] = packh2(p00, p01);
            pa[1] = packh2(p02, p03);
            pa[2] = packh2(p10, p11);
            pa[3] = packh2(p12, p13);

#pragma unroll
            for (int nt = 0; nt < 4; nt++) {
                int n = nt * 8 + r;
                uint32_t b[2];
                b[0] = *(const uint32_t*)&Vt[n * VSH + n0 + 2 * c];
                b[1] = *(const uint32_t*)&Vt[n * VSH + n0 + 2 * c + 8];
                mma_f16(oa[nt], pa, b);
            }
        }

        float inv0 = 1.f / l0, inv1 = 1.f / l1;
        int orow0 = q0 + r, orow1 = q0 + r + 8;
#pragma unroll
        for (int nt = 0; nt < 4; nt++) {
            int col = hd * DH + nt * 8 + 2 * c;
            if (orow0 < SEQ) {
                __half* op = O + ((size_t)(g * SEQ + orow0)) * E_DIM + col;
                *(__half2*)op = __floats2half2_rn(oa[nt][0] * inv0, oa[nt][1] * inv0);
            }
            if (orow1 < SEQ) {
                __half* op = O + ((size_t)(g * SEQ + orow1)) * E_DIM + col;
                *(__half2*)op = __floats2half2_rn(oa[nt][2] * inv1, oa[nt][3] * inv1);
            }
        }
    }
}

// ---------------- layernorm: warp per row, 4 rows per block ----------------
__global__ __launch_bounds__(128)
void ln4_k(const float* __restrict__ in, const float* __restrict__ gam,
           const float* __restrict__ bet, float* __restrict__ out,
           __half* __restrict__ out16)
{
    const int warp = threadIdx.x >> 5, lane = threadIdx.x & 31;
    const int row = blockIdx.x * 4 + warp;
    const size_t base = (size_t)row * E_DIM + lane * 8;
    const unsigned FULL = 0xffffffffu;

    float4 v0 = *(const float4*)&in[base];
    float4 v1 = *(const float4*)&in[base + 4];

    float s = v0.x + v0.y + v0.z + v0.w + v1.x + v1.y + v1.z + v1.w;
#pragma unroll
    for (int o = 16; o; o >>= 1) s += __shfl_xor_sync(FULL, s, o);
    float mu = s * (1.f / E_DIM);

    float d0 = v0.x - mu, d1 = v0.y - mu, d2 = v0.z - mu, d3 = v0.w - mu;
    float d4 = v1.x - mu, d5 = v1.y - mu, d6 = v1.z - mu, d7 = v1.w - mu;
    float q = d0*d0 + d1*d1 + d2*d2 + d3*d3 + d4*d4 + d5*d5 + d6*d6 + d7*d7;
#pragma unroll
    for (int o = 16; o; o >>= 1) q += __shfl_xor_sync(FULL, q, o);
    float rs = rsqrtf(q * (1.f / E_DIM) + LN_EPS);

    const int gc = lane * 8;
    float4 g0 = *(const float4*)&gam[gc];
    float4 g1 = *(const float4*)&gam[gc + 4];
    float4 b0 = *(const float4*)&bet[gc];
    float4 b1 = *(const float4*)&bet[gc + 4];

    float o0 = d0 * rs * g0.x + b0.x, o1 = d1 * rs * g0.y + b0.y;
    float o2 = d2 * rs * g0.z + b0.z, o3 = d3 * rs * g0.w + b0.w;
    float o4 = d4 * rs * g1.x + b1.x, o5 = d5 * rs * g1.y + b1.y;
    float o6 = d6 * rs * g1.z + b1.z, o7 = d7 * rs * g1.w + b1.w;

    *(float4*)&out[base]     = make_float4(o0, o1, o2, o3);
    *(float4*)&out[base + 4] = make_float4(o4, o5, o6, o7);
    __half2 h0 = __floats2half2_rn(o0, o1), h1 = __floats2half2_rn(o2, o3);
    __half2 h2 = __floats2half2_rn(o4, o5), h3 = __floats2half2_rn(o6, o7);
    uint4 hv = make_uint4(*(uint32_t*)&h0, *(uint32_t*)&h1,
                          *(uint32_t*)&h2, *(uint32_t*)&h3);
    *(uint4*)&out16[base] = hv;
}

// ---------------- final classifier -----------------------------------------
__global__ __launch_bounds__(256)
void fc_k(const float* __restrict__ w, const float* __restrict__ b,
          float* __restrict__ out)
{
    const int g = blockIdx.x, t = threadIdx.x;
    __shared__ float hrow[E_DIM];
    hrow[t] = g_h[(size_t)g * SEQ * E_DIM + t];
    __syncthreads();
    if (t < N_CLASSES) {
        float s = b[t];
        for (int e = 0; e < E_DIM; e++) s += hrow[e] * w[t * E_DIM + e];
        out[g * N_CLASSES + t] = s;
    }
}

// ---------------------------------------------------------------------------
extern "C" void kernel_launch(void* const* d_in, const int* in_sizes, int n_in,
                              void* d_out, int out_size)
{
    const float* x        = (const float*)d_in[0];
    const int*   edge_idx = (const int*)  d_in[1];
    // d_in[2] = batch (unused: layout is arange // NPG by construction)
    const float* pos_enc  = (const float*)d_in[3];
    const float* gcn_w    = (const float*)d_in[4];
    const float* gcn_b    = (const float*)d_in[5];
    const float* cls      = (const float*)d_in[6];
    const float* emb_w    = (const float*)d_in[7];
    const float* emb_b    = (const float*)d_in[8];
    const float* in_w     = (const float*)d_in[9];
    const float* in_b     = (const float*)d_in[10];
    const float* out_w    = (const float*)d_in[11];
    const float* out_b    = (const float*)d_in[12];
    const float* lin1_w   = (const float*)d_in[13];
    const float* lin1_b   = (const float*)d_in[14];
    const float* lin2_w   = (const float*)d_in[15];
    const float* lin2_b   = (const float*)d_in[16];
    const float* ln1_g    = (const float*)d_in[17];
    const float* ln1_beta = (const float*)d_in[18];
    const float* ln2_g    = (const float*)d_in[19];
    const float* ln2_beta = (const float*)d_in[20];
    const float* fc_w     = (const float*)d_in[21];
    const float* fc_b     = (const float*)d_in[22];
    float* out = (float*)d_out;

    void *p;
    float *xw, *emb, *h, *tmp;
    __half *qkv16;
    __half *x16, *gcnw16, *gcn16, *embw16, *h16, *att16, *mlp16;
    __half *inw16, *outw16, *l1w16, *l2w16;
    cudaGetSymbolAddress(&p, g_xw);    xw    = (float*)p;
    cudaGetSymbolAddress(&p, g_emb);   emb   = (float*)p;
    cudaGetSymbolAddress(&p, g_h);     h     = (float*)p;
    cudaGetSymbolAddress(&p, g_qkv);   qkv16 = (__half*)p;   // fp16 view
    cudaGetSymbolAddress(&p, g_tmp);   tmp   = (float*)p;
    cudaGetSymbolAddress(&p, g_x16);   x16   = (__half*)p;
    cudaGetSymbolAddress(&p, g_gcnw16);gcnw16= (__half*)p;
    cudaGetSymbolAddress(&p, g_gcn16); gcn16 = (__half*)p;
    cudaGetSymbolAddress(&p, g_embw16);embw16= (__half*)p;
    cudaGetSymbolAddress(&p, g_h16);   h16   = (__half*)p;
    cudaGetSymbolAddress(&p, g_att16); att16 = (__half*)p;
    cudaGetSymbolAddress(&p, g_mlp16); mlp16 = (__half*)p;
    cudaGetSymbolAddress(&p, g_inw16); inw16 = (__half*)p;
    cudaGetSymbolAddress(&p, g_outw16);outw16= (__half*)p;
    cudaGetSymbolAddress(&p, g_l1w16); l1w16 = (__half*)p;
    cudaGetSymbolAddress(&p, g_l2w16); l2w16 = (__half*)p;

    cudaFuncSetAttribute(gemm_h<0>, cudaFuncAttributeMaxDynamicSharedMemorySize, GH_SMEM);
    cudaFuncSetAttribute(gemm_h<1>, cudaFuncAttributeMaxDynamicSharedMemorySize, GH_SMEM);

    // ---- convert GCN-front operands, GCN gemm at launch index 3 ----
    cvt_k<<<(N_NODES * F_IN) / 256, 256>>>(x, x16, N_NODES * F_IN);        // 0
    cvt_k<<<(F_IN * F_IN) / 256, 256>>>(gcn_w, gcnw16, F_IN * F_IN);       // 1
    zero_cnt_k<<<N_NODES / 256, 256>>>();                                  // 2
    gemm_h<0><<<dim3(F_IN / 128, N_NODES / 128), 256, GH_SMEM>>>(          // 3
        x16, gcnw16, nullptr, nullptr, xw, nullptr, F_IN, F_IN);
    count_k<<<512, 256>>>(edge_idx);
    scan_k<<<1, 1024>>>();
    fill_k<<<512, 256>>>(edge_idx);
    gcn_gather_k<<<(N_NODES * 32) / 256, 256>>>(gcn_b);

    // ---- remaining weight conversions ----
    cvt_k<<<(E_DIM * F_IN) / 256, 256>>>(emb_w, embw16, E_DIM * F_IN);
    cvt_k<<<(N_LAYERS * 3 * E_DIM * E_DIM) / 256, 256>>>(in_w, inw16, N_LAYERS * 3 * E_DIM * E_DIM);
    cvt_k<<<(N_LAYERS * E_DIM * E_DIM) / 256, 256>>>(out_w, outw16, N_LAYERS * E_DIM * E_DIM);
    cvt_k<<<(N_LAYERS * MLP_DIM * E_DIM) / 256, 256>>>(lin1_w, l1w16, N_LAYERS * MLP_DIM * E_DIM);
    cvt_k<<<(N_LAYERS * E_DIM * MLP_DIM) / 256, 256>>>(lin2_w, l2w16, N_LAYERS * E_DIM * MLP_DIM);

    // ---- embedding + pos_enc, assemble tokens ----
    gemm_h<0><<<dim3(E_DIM / 128, N_NODES / 128), 256, GH_SMEM>>>(
        gcn16, embw16, emb_b, pos_enc, emb, nullptr, E_DIM, F_IN);
    assemble_k<<<(TOK * E_DIM) / 256, 256>>>(cls);

    // ---- transformer layers ----
    for (int l = 0; l < N_LAYERS; l++) {
        gemm_h<0><<<dim3(768 / 128, TOKP / 128), 256, GH_SMEM>>>(
            h16, inw16 + (size_t)l * 768 * E_DIM, in_b + l * 768,
            nullptr, nullptr, qkv16, 768, E_DIM);
        attn_h_k<<<N_GRAPHS * N_HEADS, 256>>>(qkv16, att16);
        gemm_h<0><<<dim3(E_DIM / 128, TOKP / 128), 256, GH_SMEM>>>(
            att16, outw16 + (size_t)l * E_DIM * E_DIM, out_b + l * E_DIM,
            h, tmp, nullptr, E_DIM, E_DIM);
        ln4_k<<<TOK / 4, 128>>>(tmp, ln1_g + l * E_DIM, ln1_beta + l * E_DIM, h, h16);
        gemm_h<1><<<dim3(MLP_DIM / 128, TOKP / 128), 256, GH_SMEM>>>(
            h16, l1w16 + (size_t)l * MLP_DIM * E_DIM, lin1_b + l * MLP_DIM,
            nullptr, nullptr, mlp16, MLP_DIM, E_DIM);
        gemm_h<0><<<dim3(E_DIM / 128, TOKP / 128), 256, GH_SMEM>>>(
            mlp16, l2w16 + (size_t)l * E_DIM * MLP_DIM, lin2_b + l * E_DIM,
            h, tmp, nullptr, E_DIM, MLP_DIM);
        ln4_k<<<TOK / 4, 128>>>(tmp, ln2_g + l * E_DIM, ln2_beta + l * E_DIM, h, h16);
    }

    // ---- classifier head ----
    fc_k<<<N_GRAPHS, 256>>>(fc_w, fc_b, out);
}

// round 17
// speedup vs baseline: 1.0400x; 1.0400x over previous
#include <cuda_runtime.h>
#include <cuda_fp16.h>
#include <math.h>
#include <stdint.h>

#define N_NODES   16384
#define N_GRAPHS  64
#define NPG       256
#define F_IN      128
#define E_DIM     256
#define N_HEADS   8
#define DH        32
#define MLP_DIM   1024
#define N_LAYERS  4
#define N_CLASSES 10
#define N_EDGES   262144
#define SEQ       257                 // NODES_PER_GRAPH + 1 (cls)
#define TOK       (N_GRAPHS * SEQ)    // 16448
#define TOKP      16512               // padded to 129*128 for 128-row tiles
#define LN_EPS    1e-5f

// ---------------- scratch (static device globals, zero-initialized) --------
__device__ float g_xw [N_NODES * F_IN];
__device__ float g_dinv[N_NODES];
__device__ float g_emb[N_NODES * E_DIM];
__device__ float g_h  [TOKP * E_DIM];
__device__ float g_qkv[TOKP * 3 * E_DIM];   // reused as fp16 qkv
// CSR for GCN gather
__device__ int g_cnt [N_NODES];
__device__ int g_base[N_NODES];
__device__ int g_cur [N_NODES];
__device__ int g_elist[N_EDGES];

// fp16 operand mirrors
__device__ __half g_x16  [N_NODES * F_IN];
__device__ __half g_gcnw16[F_IN * F_IN];
__device__ __half g_gcn16[N_NODES * F_IN];
__device__ __half g_embw16[E_DIM * F_IN];
__device__ __half g_h16  [TOKP * E_DIM];
__device__ __half g_att16[TOKP * E_DIM];
__device__ __half g_mlp16[TOKP * MLP_DIM];
__device__ __half g_inw16 [N_LAYERS * 3 * E_DIM * E_DIM];
__device__ __half g_outw16[N_LAYERS * E_DIM * E_DIM];
__device__ __half g_l1w16 [N_LAYERS * MLP_DIM * E_DIM];
__device__ __half g_l2w16 [N_LAYERS * E_DIM * MLP_DIM];

// ===================== helpers =============================================
__device__ __forceinline__ uint32_t smem_u32(const void* p) {
    return (uint32_t)__cvta_generic_to_shared(p);
}
__device__ __forceinline__ void cp16s(uint32_t dst, const void* src) {
    asm volatile("cp.async.cg.shared.global [%0], [%1], 16;\n" :: "r"(dst), "l"(src));
}
#define CP_COMMIT() asm volatile("cp.async.commit_group;\n")

__device__ __forceinline__ void mma_f16(float* d, const uint32_t* a, const uint32_t* b) {
    asm volatile(
        "mma.sync.aligned.m16n8k16.row.col.f32.f16.f16.f32 "
        "{%0,%1,%2,%3}, {%4,%5,%6,%7}, {%8,%9}, {%0,%1,%2,%3};\n"
        : "+f"(d[0]), "+f"(d[1]), "+f"(d[2]), "+f"(d[3])
        : "r"(a[0]), "r"(a[1]), "r"(a[2]), "r"(a[3]), "r"(b[0]), "r"(b[1]));
}
__device__ __forceinline__ uint32_t packh2(float x, float y) {
    __half2 h = __floats2half2_rn(x, y);
    return *(uint32_t*)&h;
}

// ===================== fp16 HMMA GEMM (R15-proven: 2-stage, K64) ============
#define HROW 72
#define STG  (128 * HROW)               // halves per matrix per stage
#define GH_SMEM (4 * STG * 2)           // 73728

template <int RELU>
__global__ __launch_bounds__(256, 2)
void gemm_h(const __half* __restrict__ A, const __half* __restrict__ B,
            const float* __restrict__ bias, const float* __restrict__ add,
            float* __restrict__ C32, __half* __restrict__ C16, int N, int K)
{
    extern __shared__ __half smh[];
    __half* As = smh;            // [2][STG]
    __half* Bs = smh + 2 * STG;  // [2][STG]

    const int tid = threadIdx.x;
    const int warp = tid >> 5, lane = tid & 31;
    const int wm = warp >> 2, wn = warp & 3;     // 2 x 4 warp grid
    const int r = lane >> 2, c = lane & 3;
    const int m0 = blockIdx.y * 128;
    const int n0 = blockIdx.x * 128;
    const int KT = K >> 6;

    float acc[4][4][4];
#pragma unroll
    for (int i = 0; i < 4; i++)
#pragma unroll
        for (int j = 0; j < 4; j++)
#pragma unroll
            for (int q = 0; q < 4; q++) acc[i][j][q] = 0.f;

    auto load_stage = [&](int kt, int s) {
        const __half* Ag = A + (size_t)m0 * K + kt * 64;
        const __half* Bg = B + (size_t)n0 * K + kt * 64;
        const uint32_t sa = smem_u32(&As[s * STG]);
        const uint32_t sb = smem_u32(&Bs[s * STG]);
#pragma unroll
        for (int i = 0; i < 4; i++) {
            int id = tid + 256 * i;
            int row = id >> 3, ch = id & 7;
            cp16s(sa + row * 144 + ch * 16, Ag + (size_t)row * K + ch * 8);
            cp16s(sb + row * 144 + ch * 16, Bg + (size_t)row * K + ch * 8);
        }
    };

    load_stage(0, 0);
    CP_COMMIT();

    for (int kt = 0; kt < KT; kt++) {
        const int s = kt & 1;
        if (kt + 1 < KT) {
            load_stage(kt + 1, s ^ 1);
            CP_COMMIT();
            asm volatile("cp.async.wait_group 1;\n");
        } else {
            asm volatile("cp.async.wait_group 0;\n");
        }
        __syncthreads();

        const uint32_t saBase = smem_u32(&As[s * STG]);
        const __half* Bst = &Bs[s * STG];
#pragma unroll
        for (int ks = 0; ks < 4; ks++) {
            uint32_t a[4][4];
#pragma unroll
            for (int ma = 0; ma < 4; ma++) {
                int mbase = wm * 64 + ma * 16;
                uint32_t addr = saBase + (mbase + (lane & 15)) * 144
                              + ks * 32 + ((lane >> 4) & 1) * 16;
                asm volatile(
                    "ldmatrix.sync.aligned.m8n8.x4.shared.b16 {%0,%1,%2,%3}, [%4];"
                    : "=r"(a[ma][0]), "=r"(a[ma][1]), "=r"(a[ma][2]), "=r"(a[ma][3])
                    : "r"(addr));
            }
            uint32_t b[4][2];
#pragma unroll
            for (int na = 0; na < 4; na++) {
                int n = wn * 32 + na * 8 + r;
                const __half* bp = Bst + n * HROW + ks * 16 + c * 2;
                b[na][0] = *(const uint32_t*)(bp);
                b[na][1] = *(const uint32_t*)(bp + 8);
            }
#pragma unroll
            for (int ma = 0; ma < 4; ma++)
#pragma unroll
                for (int na = 0; na < 4; na++)
                    mma_f16(acc[ma][na], a[ma], b[na]);
        }
        __syncthreads();
    }

#pragma unroll
    for (int ma = 0; ma < 4; ma++) {
        int mlo = m0 + wm * 64 + ma * 16 + r;
        int mhi = mlo + 8;
#pragma unroll
        for (int na = 0; na < 4; na++) {
            int n = n0 + wn * 32 + na * 8 + c * 2;
            float b0 = bias ? bias[n] : 0.f;
            float b1 = bias ? bias[n + 1] : 0.f;
            float v0 = acc[ma][na][0] + b0;
            float v1 = acc[ma][na][1] + b1;
            float v2 = acc[ma][na][2] + b0;
            float v3 = acc[ma][na][3] + b1;
            size_t ilo = (size_t)mlo * N + n;
            size_t ihi = (size_t)mhi * N + n;
            if (add) {
                float2 alo = *(const float2*)&add[ilo];
                float2 ahi = *(const float2*)&add[ihi];
                v0 += alo.x; v1 += alo.y; v2 += ahi.x; v3 += ahi.y;
            }
            if (RELU) {
                v0 = v0 > 0.f ? v0 : 0.f; v1 = v1 > 0.f ? v1 : 0.f;
                v2 = v2 > 0.f ? v2 : 0.f; v3 = v3 > 0.f ? v3 : 0.f;
            }
            if (C32) {
                *(float2*)&C32[ilo] = make_float2(v0, v1);
                *(float2*)&C32[ihi] = make_float2(v2, v3);
            }
            if (C16) {
                *(__half2*)&C16[ilo] = __floats2half2_rn(v0, v1);
                *(__half2*)&C16[ihi] = __floats2half2_rn(v2, v3);
            }
        }
    }
}

// ============ fused GEMM + bias + residual + LayerNorm (N = 256) ============
// Tile 64x256: one block owns full E_DIM rows -> LN is block-local.
// 8 warps as 1x8 (warp tile 64x32) — same fragment geometry as gemm_h.
#define FL_SMEM ((64 + 256) * HROW * 2 * 2)   // 92160 bytes

__global__ __launch_bounds__(256, 2)
void gemm_ln(const __half* __restrict__ A, const __half* __restrict__ B,
             const float* __restrict__ bias, const float* __restrict__ resid,
             const float* __restrict__ gam, const float* __restrict__ bet,
             float* __restrict__ outF, __half* __restrict__ outH, int K)
{
    extern __shared__ __half smh[];
    __half* As = smh;                   // [2][64*HROW]
    __half* Bs = smh + 2 * 64 * HROW;   // [2][256*HROW]

    const int tid = threadIdx.x;
    const int wn = tid >> 5, lane = tid & 31;
    const int r = lane >> 2, c = lane & 3;
    const int m0 = blockIdx.x * 64;
    const int KT = K >> 6;

    float acc[4][4][4];
#pragma unroll
    for (int i = 0; i < 4; i++)
#pragma unroll
        for (int j = 0; j < 4; j++)
#pragma unroll
            for (int q = 0; q < 4; q++) acc[i][j][q] = 0.f;

    auto load_stage = [&](int kt, int s) {
        const __half* Ag = A + (size_t)m0 * K + kt * 64;
        const __half* Bg = B + (size_t)kt * 64;
        const uint32_t sa = smem_u32(&As[s * 64 * HROW]);
        const uint32_t sb = smem_u32(&Bs[s * 256 * HROW]);
#pragma unroll
        for (int i = 0; i < 2; i++) {
            int id = tid + 256 * i;
            int row = id >> 3, ch = id & 7;
            cp16s(sa + row * 144 + ch * 16, Ag + (size_t)row * K + ch * 8);
        }
#pragma unroll
        for (int i = 0; i < 8; i++) {
            int id = tid + 256 * i;
            int row = id >> 3, ch = id & 7;
            cp16s(sb + row * 144 + ch * 16, Bg + (size_t)row * K + ch * 8);
        }
    };

    load_stage(0, 0);
    CP_COMMIT();

    for (int kt = 0; kt < KT; kt++) {
        const int s = kt & 1;
        if (kt + 1 < KT) {
            load_stage(kt + 1, s ^ 1);
            CP_COMMIT();
            asm volatile("cp.async.wait_group 1;\n");
        } else {
            asm volatile("cp.async.wait_group 0;\n");
        }
        __syncthreads();

        const uint32_t saBase = smem_u32(&As[s * 64 * HROW]);
        const __half* Bst = &Bs[s * 256 * HROW];
#pragma unroll
        for (int ks = 0; ks < 4; ks++) {
            uint32_t a[4][4];
#pragma unroll
            for (int ma = 0; ma < 4; ma++) {
                uint32_t addr = saBase + (ma * 16 + (lane & 15)) * 144
                              + ks * 32 + ((lane >> 4) & 1) * 16;
                asm volatile(
                    "ldmatrix.sync.aligned.m8n8.x4.shared.b16 {%0,%1,%2,%3}, [%4];"
                    : "=r"(a[ma][0]), "=r"(a[ma][1]), "=r"(a[ma][2]), "=r"(a[ma][3])
                    : "r"(addr));
            }
            uint32_t b[4][2];
#pragma unroll
            for (int na = 0; na < 4; na++) {
                int n = wn * 32 + na * 8 + r;
                const __half* bp = Bst + n * HROW + ks * 16 + c * 2;
                b[na][0] = *(const uint32_t*)(bp);
                b[na][1] = *(const uint32_t*)(bp + 8);
            }
#pragma unroll
            for (int ma = 0; ma < 4; ma++)
#pragma unroll
                for (int na = 0; na < 4; na++)
                    mma_f16(acc[ma][na], a[ma], b[na]);
        }
        __syncthreads();
    }

    // ---- epilogue: bias + residual, then block-local LayerNorm ----
    const unsigned FULL = 0xffffffffu;
#pragma unroll
    for (int ma = 0; ma < 4; ma++) {
        int rlo = m0 + ma * 16 + r;
        int rhi = rlo + 8;
#pragma unroll
        for (int na = 0; na < 4; na++) {
            int n = wn * 32 + na * 8 + 2 * c;
            float b0 = bias[n], b1 = bias[n + 1];
            float2 alo = *(const float2*)&resid[(size_t)rlo * E_DIM + n];
            float2 ahi = *(const float2*)&resid[(size_t)rhi * E_DIM + n];
            acc[ma][na][0] += b0 + alo.x;
            acc[ma][na][1] += b1 + alo.y;
            acc[ma][na][2] += b0 + ahi.x;
            acc[ma][na][3] += b1 + ahi.y;
        }
    }

    float* red = (float*)smh;        // [0:512) sums, [512:1024) sumsq, [1024..] mu/rs
#pragma unroll
    for (int ma = 0; ma < 4; ma++) {
        float s0 = 0.f, s1 = 0.f, q0 = 0.f, q1 = 0.f;
#pragma unroll
        for (int na = 0; na < 4; na++) {
            float v0 = acc[ma][na][0], v1 = acc[ma][na][1];
            float v2 = acc[ma][na][2], v3 = acc[ma][na][3];
            s0 += v0 + v1; q0 += v0 * v0 + v1 * v1;
            s1 += v2 + v3; q1 += v2 * v2 + v3 * v3;
        }
        s0 += __shfl_xor_sync(FULL, s0, 1); s0 += __shfl_xor_sync(FULL, s0, 2);
        s1 += __shfl_xor_sync(FULL, s1, 1); s1 += __shfl_xor_sync(FULL, s1, 2);
        q0 += __shfl_xor_sync(FULL, q0, 1); q0 += __shfl_xor_sync(FULL, q0, 2);
        q1 += __shfl_xor_sync(FULL, q1, 1); q1 += __shfl_xor_sync(FULL, q1, 2);
        if (c == 0) {
            red[wn * 64 + ma * 16 + r]           = s0;
            red[wn * 64 + ma * 16 + r + 8]       = s1;
            red[512 + wn * 64 + ma * 16 + r]     = q0;
            red[512 + wn * 64 + ma * 16 + r + 8] = q1;
        }
    }
    __syncthreads();
    if (tid < 64) {
        float sum = 0.f, sq = 0.f;
#pragma unroll
        for (int w = 0; w < 8; w++) { sum += red[w * 64 + tid]; sq += red[512 + w * 64 + tid]; }
        float mu = sum * (1.f / E_DIM);
        float var = sq * (1.f / E_DIM) - mu * mu;
        red[1024 + tid] = mu;
        red[1088 + tid] = rsqrtf(var + LN_EPS);
    }
    __syncthreads();

#pragma unroll
    for (int ma = 0; ma < 4; ma++) {
        int lr0 = ma * 16 + r, lr1 = lr0 + 8;
        float mu0 = red[1024 + lr0], rs0 = red[1088 + lr0];
        float mu1 = red[1024 + lr1], rs1 = red[1088 + lr1];
        int glo = m0 + lr0, ghi = m0 + lr1;
#pragma unroll
        for (int na = 0; na < 4; na++) {
            int n = wn * 32 + na * 8 + 2 * c;
            float gm0 = gam[n], gm1 = gam[n + 1];
            float be0 = bet[n], be1 = bet[n + 1];
            float o0 = (acc[ma][na][0] - mu0) * rs0 * gm0 + be0;
            float o1 = (acc[ma][na][1] - mu0) * rs0 * gm1 + be1;
            float o2 = (acc[ma][na][2] - mu1) * rs1 * gm0 + be0;
            float o3 = (acc[ma][na][3] - mu1) * rs1 * gm1 + be1;
            size_t ilo = (size_t)glo * E_DIM + n;
            size_t ihi = (size_t)ghi * E_DIM + n;
            *(float2*)&outF[ilo] = make_float2(o0, o1);
            *(float2*)&outF[ihi] = make_float2(o2, o3);
            *(__half2*)&outH[ilo] = __floats2half2_rn(o0, o1);
            *(__half2*)&outH[ihi] = __floats2half2_rn(o2, o3);
        }
    }
}

// ---------------- fp32 -> fp16 convert -------------------------------------
__global__ void cvt_k(const float* __restrict__ s, __half* __restrict__ d, int n) {
    int i = blockIdx.x * blockDim.x + threadIdx.x;
    if (i < n) d[i] = __float2half_rn(s[i]);
}

// ---------------- GCN: CSR build + gather ----------------------------------
__global__ void zero_cnt_k() {
    int i = blockIdx.x * blockDim.x + threadIdx.x;
    if (i < N_NODES) g_cnt[i] = 0;
}
__global__ void count_k(const int* __restrict__ ei) {
    int i = blockIdx.x * blockDim.x + threadIdx.x;
    for (; i < N_EDGES; i += gridDim.x * blockDim.x)
        atomicAdd(&g_cnt[ei[N_EDGES + i]], 1);
}
__global__ __launch_bounds__(1024)
void scan_k() {
    const int t = threadIdx.x, lane = t & 31, wid = t >> 5;
    const unsigned FULL = 0xffffffffu;
    __shared__ int wsum[32];

    int local[16];
    int s = 0;
#pragma unroll
    for (int i = 0; i < 16; i++) { local[i] = s; s += g_cnt[t * 16 + i]; }

    int v = s;
#pragma unroll
    for (int o = 1; o < 32; o <<= 1) {
        int n = __shfl_up_sync(FULL, v, o);
        if (lane >= o) v += n;
    }
    if (lane == 31) wsum[wid] = v;
    __syncthreads();
    if (wid == 0) {
        int w = wsum[lane];
#pragma unroll
        for (int o = 1; o < 32; o <<= 1) {
            int n = __shfl_up_sync(FULL, w, o);
            if (lane >= o) w += n;
        }
        wsum[lane] = w;
    }
    __syncthreads();
    int chunk_base = v - s + (wid ? wsum[wid - 1] : 0);
#pragma unroll
    for (int i = 0; i < 16; i++) {
        int idx = t * 16 + i;
        int b = chunk_base + local[i];
        g_base[idx] = b;
        g_cur[idx]  = b;
        g_dinv[idx] = rsqrtf((float)g_cnt[idx] + 1.0f);
    }
}
__global__ void fill_k(const int* __restrict__ ei) {
    int i = blockIdx.x * blockDim.x + threadIdx.x;
    for (; i < N_EDGES; i += gridDim.x * blockDim.x) {
        int col = ei[N_EDGES + i];
        int pos = atomicAdd(&g_cur[col], 1);
        g_elist[pos] = ei[i];
    }
}
__global__ __launch_bounds__(256)
void gcn_gather_k(const float* __restrict__ bias) {
    const int node = (blockIdx.x * blockDim.x + threadIdx.x) >> 5;
    const int lane = threadIdx.x & 31;

    const float dc = g_dinv[node];
    float4 acc = *(const float4*)(g_xw + (size_t)node * F_IN + lane * 4);
    float sc = dc * dc;
    acc.x *= sc; acc.y *= sc; acc.z *= sc; acc.w *= sc;

    const int nv = g_cnt[node];
    const int b0 = g_base[node];
    for (int i = 0; i < nv; i++) {
        int row = g_elist[b0 + i];
        float nm = dc * g_dinv[row];
        float4 v = *(const float4*)(g_xw + (size_t)row * F_IN + lane * 4);
        acc.x += nm * v.x; acc.y += nm * v.y;
        acc.z += nm * v.z; acc.w += nm * v.w;
    }

    float4 bb = *(const float4*)(bias + lane * 4);
    acc.x += bb.x; acc.y += bb.y; acc.z += bb.z; acc.w += bb.w;
    acc.x = acc.x > 0.f ? acc.x : 0.f;
    acc.y = acc.y > 0.f ? acc.y : 0.f;
    acc.z = acc.z > 0.f ? acc.z : 0.f;
    acc.w = acc.w > 0.f ? acc.w : 0.f;

    __half2 h0 = __floats2half2_rn(acc.x, acc.y);
    __half2 h1 = __floats2half2_rn(acc.z, acc.w);
    *(uint2*)(g_gcn16 + (size_t)node * F_IN + lane * 4) =
        make_uint2(*(uint32_t*)&h0, *(uint32_t*)&h1);
}

// ---------------- assemble H (cls token + embedded nodes) ------------------
__global__ void assemble_k(const float* __restrict__ cls) {
    int idx = blockIdx.x * blockDim.x + threadIdx.x;   // TOK*E_DIM exact
    int row = idx >> 8, col = idx & 255;
    int g = row / SEQ, s = row - g * SEQ;
    float v = (s == 0) ? cls[col]
                       : g_emb[((size_t)(g * NPG + s - 1)) * E_DIM + col];
    g_h[idx] = v;
    g_h16[idx] = __float2half_rn(v);
}

// ============== fp16 flash attention: block per (graph, head) ===============
#define SEQP2 272
#define KSH 40          // Ks stride in halves
#define VSH 280         // Vt stride in halves

__global__ __launch_bounds__(256)
void attn_h_k(const __half* __restrict__ qkv, __half* __restrict__ O)
{
    const int g  = blockIdx.x >> 3;
    const int hd = blockIdx.x & 7;
    __shared__ __half Ks[SEQP2 * KSH];   // [key][d]
    __shared__ __half Vt[32 * VSH];      // [d][key]

    const int tid = threadIdx.x, warp = tid >> 5, lane = tid & 31;
    const int r = lane >> 2, c = lane & 3;
    const float scale = 0.17677669529663687f;   // 1/sqrt(32)
    const unsigned FULL = 0xffffffffu;

    for (int i = tid; i < SEQP2 * 32; i += 256) {
        int key = i >> 5, d = i & 31;
        __half kv = __float2half_rn(0.f), vv = kv;
        if (key < SEQ) {
            const __half* p = qkv + ((size_t)(g * SEQ + key)) * 768 + E_DIM + hd * DH + d;
            kv = p[0]; vv = p[E_DIM];
        }
        Ks[key * KSH + d] = kv;
        Vt[d * VSH + key] = vv;
    }
    __syncthreads();

    for (int qt = warp; qt < 17; qt += 8) {
        const int q0 = qt * 16;
        int row0 = q0 + r;      if (row0 > 256) row0 = 256;
        int row1 = q0 + r + 8;  if (row1 > 256) row1 = 256;
        const __half* Q0 = qkv + ((size_t)(g * SEQ + row0)) * 768 + hd * DH;
        const __half* Q1 = qkv + ((size_t)(g * SEQ + row1)) * 768 + hd * DH;

        uint32_t qa[2][4];
#pragma unroll
        for (int ks = 0; ks < 2; ks++) {
            qa[ks][0] = *(const uint32_t*)&Q0[ks * 16 + 2 * c];
            qa[ks][1] = *(const uint32_t*)&Q1[ks * 16 + 2 * c];
            qa[ks][2] = *(const uint32_t*)&Q0[ks * 16 + 2 * c + 8];
            qa[ks][3] = *(const uint32_t*)&Q1[ks * 16 + 2 * c + 8];
        }

        float m0 = -1e30f, m1 = -1e30f, l0 = 0.f, l1 = 0.f;
        float oa[4][4];
#pragma unroll
        for (int nt = 0; nt < 4; nt++)
#pragma unroll
            for (int q = 0; q < 4; q++) oa[nt][q] = 0.f;

        for (int n0 = 0; n0 < SEQP2; n0 += 16) {
            float st[2][4] = {{0.f,0.f,0.f,0.f},{0.f,0.f,0.f,0.f}};
#pragma unroll
            for (int tile = 0; tile < 2; tile++) {
                int key = n0 + tile * 8 + r;
#pragma unroll
                for (int ks = 0; ks < 2; ks++) {
                    uint32_t b[2];
                    b[0] = *(const uint32_t*)&Ks[key * KSH + ks * 16 + 2 * c];
                    b[1] = *(const uint32_t*)&Ks[key * KSH + ks * 16 + 2 * c + 8];
                    mma_f16(st[tile], qa[ks], b);
                }
            }
#pragma unroll
            for (int tile = 0; tile < 2; tile++) {
                int col = n0 + tile * 8 + 2 * c;
                st[tile][0] = (col     < SEQ) ? st[tile][0] * scale : -1e30f;
                st[tile][1] = (col + 1 < SEQ) ? st[tile][1] * scale : -1e30f;
                st[tile][2] = (col     < SEQ) ? st[tile][2] * scale : -1e30f;
                st[tile][3] = (col + 1 < SEQ) ? st[tile][3] * scale : -1e30f;
            }

            float cm0 = fmaxf(fmaxf(st[0][0], st[0][1]), fmaxf(st[1][0], st[1][1]));
            float cm1 = fmaxf(fmaxf(st[0][2], st[0][3]), fmaxf(st[1][2], st[1][3]));
            cm0 = fmaxf(cm0, __shfl_xor_sync(FULL, cm0, 1));
            cm0 = fmaxf(cm0, __shfl_xor_sync(FULL, cm0, 2));
            cm1 = fmaxf(cm1, __shfl_xor_sync(FULL, cm1, 1));
            cm1 = fmaxf(cm1, __shfl_xor_sync(FULL, cm1, 2));
            float nm0 = fmaxf(m0, cm0), nm1 = fmaxf(m1, cm1);
            float al0 = __expf(m0 - nm0), al1 = __expf(m1 - nm1);
            m0 = nm0; m1 = nm1;
            float p00 = __expf(st[0][0] - nm0), p01 = __expf(st[0][1] - nm0);
            float p02 = __expf(st[0][2] - nm1), p03 = __expf(st[0][3] - nm1);
            float p10 = __expf(st[1][0] - nm0), p11 = __expf(st[1][1] - nm0);
            float p12 = __expf(st[1][2] - nm1), p13 = __expf(st[1][3] - nm1);
            float rs0 = p00 + p01 + p10 + p11;
            float rs1 = p02 + p03 + p12 + p13;
            rs0 += __shfl_xor_sync(FULL, rs0, 1);
            rs0 += __shfl_xor_sync(FULL, rs0, 2);
            rs1 += __shfl_xor_sync(FULL, rs1, 1);
            rs1 += __shfl_xor_sync(FULL, rs1, 2);
            l0 = l0 * al0 + rs0;
            l1 = l1 * al1 + rs1;
#pragma unroll
            for (int nt = 0; nt < 4; nt++) {
                oa[nt][0] *= al0; oa[nt][1] *= al0;
                oa[nt][2] *= al1; oa[nt][3] *= al1;
            }

            uint32_t pa[4];
            pa[0] = packh2(p00, p01);
            pa[1] = packh2(p02, p03);
            pa[2] = packh2(p10, p11);
            pa[3] = packh2(p12, p13);

#pragma unroll
            for (int nt = 0; nt < 4; nt++) {
                int n = nt * 8 + r;
                uint32_t b[2];
                b[0] = *(const uint32_t*)&Vt[n * VSH + n0 + 2 * c];
                b[1] = *(const uint32_t*)&Vt[n * VSH + n0 + 2 * c + 8];
                mma_f16(oa[nt], pa, b);
            }
        }

        float inv0 = 1.f / l0, inv1 = 1.f / l1;
        int orow0 = q0 + r, orow1 = q0 + r + 8;
#pragma unroll
        for (int nt = 0; nt < 4; nt++) {
            int col = hd * DH + nt * 8 + 2 * c;
            if (orow0 < SEQ) {
                __half* op = O + ((size_t)(g * SEQ + orow0)) * E_DIM + col;
                *(__half2*)op = __floats2half2_rn(oa[nt][0] * inv0, oa[nt][1] * inv0);
            }
            if (orow1 < SEQ) {
                __half* op = O + ((size_t)(g * SEQ + orow1)) * E_DIM + col;
                *(__half2*)op = __floats2half2_rn(oa[nt][2] * inv1, oa[nt][3] * inv1);
            }
        }
    }
}

// ---------------- final classifier -----------------------------------------
__global__ __launch_bounds__(256)
void fc_k(const float* __restrict__ w, const float* __restrict__ b,
          float* __restrict__ out)
{
    const int g = blockIdx.x, t = threadIdx.x;
    __shared__ float hrow[E_DIM];
    hrow[t] = g_h[(size_t)g * SEQ * E_DIM + t];
    __syncthreads();
    if (t < N_CLASSES) {
        float s = b[t];
        for (int e = 0; e < E_DIM; e++) s += hrow[e] * w[t * E_DIM + e];
        out[g * N_CLASSES + t] = s;
    }
}

// ---------------------------------------------------------------------------
extern "C" void kernel_launch(void* const* d_in, const int* in_sizes, int n_in,
                              void* d_out, int out_size)
{
    const float* x        = (const float*)d_in[0];
    const int*   edge_idx = (const int*)  d_in[1];
    // d_in[2] = batch (unused: layout is arange // NPG by construction)
    const float* pos_enc  = (const float*)d_in[3];
    const float* gcn_w    = (const float*)d_in[4];
    const float* gcn_b    = (const float*)d_in[5];
    const float* cls      = (const float*)d_in[6];
    const float* emb_w    = (const float*)d_in[7];
    const float* emb_b    = (const float*)d_in[8];
    const float* in_w     = (const float*)d_in[9];
    const float* in_b     = (const float*)d_in[10];
    const float* out_w    = (const float*)d_in[11];
    const float* out_b    = (const float*)d_in[12];
    const float* lin1_w   = (const float*)d_in[13];
    const float* lin1_b   = (const float*)d_in[14];
    const float* lin2_w   = (const float*)d_in[15];
    const float* lin2_b   = (const float*)d_in[16];
    const float* ln1_g    = (const float*)d_in[17];
    const float* ln1_beta = (const float*)d_in[18];
    const float* ln2_g    = (const float*)d_in[19];
    const float* ln2_beta = (const float*)d_in[20];
    const float* fc_w     = (const float*)d_in[21];
    const float* fc_b     = (const float*)d_in[22];
    float* out = (float*)d_out;

    void *p;
    float *xw, *emb, *h;
    __half *qkv16;
    __half *x16, *gcnw16, *gcn16, *embw16, *h16, *att16, *mlp16;
    __half *inw16, *outw16, *l1w16, *l2w16;
    cudaGetSymbolAddress(&p, g_xw);    xw    = (float*)p;
    cudaGetSymbolAddress(&p, g_emb);   emb   = (float*)p;
    cudaGetSymbolAddress(&p, g_h);     h     = (float*)p;
    cudaGetSymbolAddress(&p, g_qkv);   qkv16 = (__half*)p;   // fp16 view
    cudaGetSymbolAddress(&p, g_x16);   x16   = (__half*)p;
    cudaGetSymbolAddress(&p, g_gcnw16);gcnw16= (__half*)p;
    cudaGetSymbolAddress(&p, g_gcn16); gcn16 = (__half*)p;
    cudaGetSymbolAddress(&p, g_embw16);embw16= (__half*)p;
    cudaGetSymbolAddress(&p, g_h16);   h16   = (__half*)p;
    cudaGetSymbolAddress(&p, g_att16); att16 = (__half*)p;
    cudaGetSymbolAddress(&p, g_mlp16); mlp16 = (__half*)p;
    cudaGetSymbolAddress(&p, g_inw16); inw16 = (__half*)p;
    cudaGetSymbolAddress(&p, g_outw16);outw16= (__half*)p;
    cudaGetSymbolAddress(&p, g_l1w16); l1w16 = (__half*)p;
    cudaGetSymbolAddress(&p, g_l2w16); l2w16 = (__half*)p;

    cudaFuncSetAttribute(gemm_h<0>, cudaFuncAttributeMaxDynamicSharedMemorySize, GH_SMEM);
    cudaFuncSetAttribute(gemm_h<1>, cudaFuncAttributeMaxDynamicSharedMemorySize, GH_SMEM);
    cudaFuncSetAttribute(gemm_ln, cudaFuncAttributeMaxDynamicSharedMemorySize, FL_SMEM);

    // ---- convert GCN-front operands, GCN gemm at launch index 3 ----
    cvt_k<<<(N_NODES * F_IN) / 256, 256>>>(x, x16, N_NODES * F_IN);        // 0
    cvt_k<<<(F_IN * F_IN) / 256, 256>>>(gcn_w, gcnw16, F_IN * F_IN);       // 1
    zero_cnt_k<<<N_NODES / 256, 256>>>();                                  // 2
    gemm_h<0><<<dim3(F_IN / 128, N_NODES / 128), 256, GH_SMEM>>>(          // 3
        x16, gcnw16, nullptr, nullptr, xw, nullptr, F_IN, F_IN);
    count_k<<<512, 256>>>(edge_idx);
    scan_k<<<1, 1024>>>();
    fill_k<<<512, 256>>>(edge_idx);
    gcn_gather_k<<<(N_NODES * 32) / 256, 256>>>(gcn_b);

    // ---- remaining weight conversions ----
    cvt_k<<<(E_DIM * F_IN) / 256, 256>>>(emb_w, embw16, E_DIM * F_IN);
    cvt_k<<<(N_LAYERS * 3 * E_DIM * E_DIM) / 256, 256>>>(in_w, inw16, N_LAYERS * 3 * E_DIM * E_DIM);
    cvt_k<<<(N_LAYERS * E_DIM * E_DIM) / 256, 256>>>(out_w, outw16, N_LAYERS * E_DIM * E_DIM);
    cvt_k<<<(N_LAYERS * MLP_DIM * E_DIM) / 256, 256>>>(lin1_w, l1w16, N_LAYERS * MLP_DIM * E_DIM);
    cvt_k<<<(N_LAYERS * E_DIM * MLP_DIM) / 256, 256>>>(lin2_w, l2w16, N_LAYERS * E_DIM * MLP_DIM);

    // ---- embedding + pos_enc, assemble tokens ----
    gemm_h<0><<<dim3(E_DIM / 128, N_NODES / 128), 256, GH_SMEM>>>(
        gcn16, embw16, emb_b, pos_enc, emb, nullptr, E_DIM, F_IN);
    assemble_k<<<(TOK * E_DIM) / 256, 256>>>(cls);

    // ---- transformer layers ----
    for (int l = 0; l < N_LAYERS; l++) {
        gemm_h<0><<<dim3(768 / 128, TOKP / 128), 256, GH_SMEM>>>(
            h16, inw16 + (size_t)l * 768 * E_DIM, in_b + l * 768,
            nullptr, nullptr, qkv16, 768, E_DIM);
        attn_h_k<<<N_GRAPHS * N_HEADS, 256>>>(qkv16, att16);
        gemm_ln<<<TOKP / 64, 256, FL_SMEM>>>(
            att16, outw16 + (size_t)l * E_DIM * E_DIM, out_b + l * E_DIM,
            h, ln1_g + l * E_DIM, ln1_beta + l * E_DIM, h, h16, E_DIM);
        gemm_h<1><<<dim3(MLP_DIM / 128, TOKP / 128), 256, GH_SMEM>>>(
            h16, l1w16 + (size_t)l * MLP_DIM * E_DIM, lin1_b + l * MLP_DIM,
            nullptr, nullptr, mlp16, MLP_DIM, E_DIM);
        gemm_ln<<<TOKP / 64, 256, FL_SMEM>>>(
            mlp16, l2w16 + (size_t)l * E_DIM * MLP_DIM, lin2_b + l * E_DIM,
            h, ln2_g + l * E_DIM, ln2_beta + l * E_DIM, h, h16, MLP_DIM);
    }

    // ---- classifier head ----
    fc_k<<<N_GRAPHS, 256>>>(fc_w, fc_b, out);
}